// round 12
// baseline (speedup 1.0000x reference)
#include <cuda_runtime.h>
#include <math.h>

#define NB 4
#define QN 10000

// g_acc slots: 0..2 pg, 3..5 gp, 6..8 edge, 9..11 normal, 12..14 lap,
//              15..17 move, 18 bce
__device__ float g_acc[20];
__device__ unsigned int       g_min32[9720];   // pg mins, n>0: lvl bases {0,468,2322}, idx (n-1)*P+p
__device__ unsigned long long g_min64[3240];   // pg batch-0: (key<<32)|gt_idx, lvl bases {0,156,774}
__device__ unsigned int       g_gp_min[40000]; // gp lvl2 mins: n*QN + q

__device__ __forceinline__ unsigned int fkey(float f) {
    unsigned int u = __float_as_uint(f);
    return (u & 0x80000000u) ? ~u : (u | 0x80000000u);
}
__device__ __forceinline__ float funkey(unsigned int k) {
    unsigned int u = (k & 0x80000000u) ? (k ^ 0x80000000u) : ~k;
    return __uint_as_float(u);
}
__device__ __forceinline__ float warpSum(float v) {
    #pragma unroll
    for (int o = 16; o > 0; o >>= 1) v += __shfl_down_sync(0xffffffffu, v, o);
    return v;
}

// ---------------------------------------------------------------------------
__global__ void init_kernel() {
    const int i = blockIdx.x * blockDim.x + threadIdx.x;
    if (i < 20) g_acc[i] = 0.0f;
    if (i < 9720) g_min32[i] = 0xFFFFFFFFu;
    if (i < 3240) g_min64[i] = 0xFFFFFFFFFFFFFFFFull;
    if (i < 40000) g_gp_min[i] = 0xFFFFFFFFu;
}

// ---------------------------------------------------------------------------
// Main kernel (256 threads), 2 query points per thread in pg and gp.
// Block roles:
//   [0,320)   pg  (lvl0 [0,40): pc=1 chunk; lvl1 [40,120): pc(2); lvl2 [120,320): pc(5))
//             per lvl: r -> gc = r%10, n = (r/10)%4, pc = r/40; 512 pred pts/block
//   [320,720) gp  (lvl0 [0,80), lvl1 [80,160), lvl2 [160,400) of r2=bid-320)
//             512 GT queries/block; lvl0/1 full level one chunk (direct sum),
//             lvl2 3 chunks of 822 (atomicMin scratch)
//   [720,771) lap+move
//   [771,963) bce (grid-stride)
// Inner loops track min of (|pt|^2 - 2*dot); own |x|^2 added once at the end.
// ---------------------------------------------------------------------------
__global__ void __launch_bounds__(256) main_kernel(
    const float* __restrict__ p0, const float* __restrict__ p1, const float* __restrict__ p2,
    const float* __restrict__ be0, const float* __restrict__ be1, const float* __restrict__ be2,
    const int* __restrict__ l0, const int* __restrict__ l1, const int* __restrict__ l2i,
    const float* __restrict__ gt,
    const float* __restrict__ gt_img, const float* __restrict__ reconst) {
    __shared__ float4 sq[1000];
    const int bid = blockIdx.x;
    const int tix = threadIdx.x;

    if (bid < 320) {
        // ----- pg: two pred points per thread, min over a 1000-pt GT chunk -----
        int r, P, lvl;
        const float* pred;
        if (bid < 40)       { lvl = 0; r = bid;       P = 156;  pred = p0; }
        else if (bid < 120) { lvl = 1; r = bid - 40;  P = 618;  pred = p1; }
        else                { lvl = 2; r = bid - 120; P = 2466; pred = p2; }
        const int gc = r % 10;
        const int n  = (r / 10) % NB;
        const int pc = r / 40;
        const int pA = pc * 512 + tix;
        const int pB = pA + 256;
        const bool vA = (pA < P);
        const bool vB = (pB < P);
        const int base32[3] = {0, 468, 2322};
        const int base64[3] = {0, 156, 774};

        const float* g = gt + ((size_t)n * QN + gc * 1000) * 3;
        for (int t = tix; t < 1000; t += 256) {
            const float qx = g[3 * t + 0];
            const float qy = g[3 * t + 1];
            const float qz = g[3 * t + 2];
            sq[t] = make_float4(qx, qy, qz, qx * qx + qy * qy + qz * qz);
        }
        __syncthreads();
        if (!vA) return;   // pB >= pA, so vA false implies vB false

        float axm = 0.f, aym = 0.f, azm = 0.f, ax2 = 0.f;
        float bxm = 0.f, bym = 0.f, bzm = 0.f, bx2 = 0.f;
        {
            const float* pp = pred + ((size_t)n * P + pA) * 3;
            const float x = pp[0], y = pp[1], z = pp[2];
            ax2 = x * x + y * y + z * z;
            axm = -2.f * x; aym = -2.f * y; azm = -2.f * z;
        }
        if (vB) {
            const float* pp = pred + ((size_t)n * P + pB) * 3;
            const float x = pp[0], y = pp[1], z = pp[2];
            bx2 = x * x + y * y + z * z;
            bxm = -2.f * x; bym = -2.f * y; bzm = -2.f * z;
        }

        if (n == 0) {
            // argmin path: 2 chains per point (even/odd t)
            float a0 = 3.4e38f, a1 = 3.4e38f, b0 = 3.4e38f, b1 = 3.4e38f;
            int ai0 = 0, ai1 = 1, bi0 = 0, bi1 = 1;
            for (int t = 0; t < 1000; t += 2) {
                const float4 q0 = sq[t + 0];
                const float4 q1 = sq[t + 1];
                const float dA0 = fmaf(axm, q0.x, fmaf(aym, q0.y, fmaf(azm, q0.z, q0.w)));
                const float dA1 = fmaf(axm, q1.x, fmaf(aym, q1.y, fmaf(azm, q1.z, q1.w)));
                const float dB0 = fmaf(bxm, q0.x, fmaf(bym, q0.y, fmaf(bzm, q0.z, q0.w)));
                const float dB1 = fmaf(bxm, q1.x, fmaf(bym, q1.y, fmaf(bzm, q1.z, q1.w)));
                if (dA0 < a0) { a0 = dA0; ai0 = t; }
                if (dA1 < a1) { a1 = dA1; ai1 = t + 1; }
                if (dB0 < b0) { b0 = dB0; bi0 = t; }
                if (dB1 < b1) { b1 = dB1; bi1 = t + 1; }
            }
            {
                float best = a0; int bi = ai0;
                if (a1 < best || (a1 == best && ai1 < bi)) { best = a1; bi = ai1; }
                const unsigned int key = fkey(ax2 + best);
                atomicMin(&g_min64[base64[lvl] + pA],
                          ((unsigned long long)key << 32) | (unsigned int)(gc * 1000 + bi));
            }
            if (vB) {
                float best = b0; int bi = bi0;
                if (b1 < best || (b1 == best && bi1 < bi)) { best = b1; bi = bi1; }
                const unsigned int key = fkey(bx2 + best);
                atomicMin(&g_min64[base64[lvl] + pB],
                          ((unsigned long long)key << 32) | (unsigned int)(gc * 1000 + bi));
            }
        } else {
            float a0 = 3.4e38f, a1 = 3.4e38f, b0 = 3.4e38f, b1 = 3.4e38f;
            for (int t = 0; t < 1000; t += 2) {
                const float4 q0 = sq[t + 0];
                const float4 q1 = sq[t + 1];
                a0 = fminf(a0, fmaf(axm, q0.x, fmaf(aym, q0.y, fmaf(azm, q0.z, q0.w))));
                a1 = fminf(a1, fmaf(axm, q1.x, fmaf(aym, q1.y, fmaf(azm, q1.z, q1.w))));
                b0 = fminf(b0, fmaf(bxm, q0.x, fmaf(bym, q0.y, fmaf(bzm, q0.z, q0.w))));
                b1 = fminf(b1, fmaf(bxm, q1.x, fmaf(bym, q1.y, fmaf(bzm, q1.z, q1.w))));
            }
            atomicMin(&g_min32[base32[lvl] + (n - 1) * P + pA], fkey(ax2 + fminf(a0, a1)));
            if (vB)
                atomicMin(&g_min32[base32[lvl] + (n - 1) * P + pB], fkey(bx2 + fminf(b0, b1)));
        }
    } else if (bid < 720) {
        // ----- gp: two GT queries per thread, min over pred chunk -----
        const int r = bid - 320;
        int lvl, rr;
        if (r < 80)       { lvl = 0; rr = r; }
        else if (r < 160) { lvl = 1; rr = r - 80; }
        else              { lvl = 2; rr = r - 160; }
        int P; const float* pred;
        if (lvl == 0)      { P = 156;  pred = p0; }
        else if (lvl == 1) { P = 618;  pred = p1; }
        else               { P = 2466; pred = p2; }
        const int qc = rr % 20;
        const int t2 = rr / 20;
        const int n  = t2 % NB;
        const int pc = t2 / NB;              // 0 for lvl0/1; 0..2 for lvl2
        const int start = pc * 822;
        const int cnt = (lvl == 2) ? 822 : P;   // 3*822 = 2466 exact

        const float* pr = pred + ((size_t)n * P + start) * 3;
        for (int t = tix; t < cnt; t += 256) {
            const float x = pr[3 * t + 0];
            const float y = pr[3 * t + 1];
            const float z = pr[3 * t + 2];
            sq[t] = make_float4(x, y, z, x * x + y * y + z * z);
        }
        __syncthreads();

        const int qA = qc * 512 + tix;
        const int qB = qA + 256;
        const bool vA = (qA < QN);
        const bool vB = (qB < QN);

        float axm = 0.f, aym = 0.f, azm = 0.f, aq2 = 0.f;
        float bxm = 0.f, bym = 0.f, bzm = 0.f, bq2 = 0.f;
        if (vA) {
            const float* gq = gt + ((size_t)n * QN + qA) * 3;
            const float x = gq[0], y = gq[1], z = gq[2];
            aq2 = x * x + y * y + z * z;
            axm = -2.f * x; aym = -2.f * y; azm = -2.f * z;
        }
        if (vB) {
            const float* gq = gt + ((size_t)n * QN + qB) * 3;
            const float x = gq[0], y = gq[1], z = gq[2];
            bq2 = x * x + y * y + z * z;
            bxm = -2.f * x; bym = -2.f * y; bzm = -2.f * z;
        }

        float a0 = 3.4e38f, a1 = 3.4e38f, b0 = 3.4e38f, b1 = 3.4e38f;
        int t = 0;
        for (; t + 2 <= cnt; t += 2) {
            const float4 v0 = sq[t + 0];
            const float4 v1 = sq[t + 1];
            a0 = fminf(a0, fmaf(axm, v0.x, fmaf(aym, v0.y, fmaf(azm, v0.z, v0.w))));
            a1 = fminf(a1, fmaf(axm, v1.x, fmaf(aym, v1.y, fmaf(azm, v1.z, v1.w))));
            b0 = fminf(b0, fmaf(bxm, v0.x, fmaf(bym, v0.y, fmaf(bzm, v0.z, v0.w))));
            b1 = fminf(b1, fmaf(bxm, v1.x, fmaf(bym, v1.y, fmaf(bzm, v1.z, v1.w))));
        }
        if (t < cnt) {
            const float4 v = sq[t];
            a0 = fminf(a0, fmaf(axm, v.x, fmaf(aym, v.y, fmaf(azm, v.z, v.w))));
            b0 = fminf(b0, fmaf(bxm, v.x, fmaf(bym, v.y, fmaf(bzm, v.z, v.w))));
        }
        const float bestA = aq2 + fminf(a0, a1);
        const float bestB = bq2 + fminf(b0, b1);

        if (lvl < 2) {
            float s = (vA ? bestA : 0.f) + (vB ? bestB : 0.f);
            s = warpSum(s);
            if ((tix & 31) == 0) atomicAdd(&g_acc[3 + lvl], s);
        } else {
            if (vA) atomicMin(&g_gp_min[n * QN + qA], fkey(bestA));
            if (vB) atomicMin(&g_gp_min[n * QN + qB], fkey(bestB));
        }
    } else if (bid < 771) {
        // ----- laplace + move -----
        int i = (bid - 720) * 256 + tix;
        float sl = 0.f, sm = 0.f;
        int lvl = -1;
        if (i < 12960) {
            int P; const float* pred; const float* bef; const int* lap;
            if (i < 624)       { lvl = 0; P = 156;  pred = p0; bef = be0; lap = l0; }
            else if (i < 3096) { lvl = 1; P = 618;  pred = p1; bef = be1; lap = l1; i -= 624; }
            else               { lvl = 2; P = 2466; pred = p2; bef = be2; lap = l2i; i -= 3096; }
            const int p = i % P;
            const int n = i / P;
            const int* lr = lap + (size_t)p * 10;
            const float invc = 1.f / (float)lr[9];
            const float* B  = bef  + (size_t)n * P * 3;
            const float* Pr = pred + (size_t)n * P * 3;
            float sbx = 0.f, sby = 0.f, sbz = 0.f;
            float spx = 0.f, spy = 0.f, spz = 0.f;
            #pragma unroll
            for (int j = 0; j < 8; j++) {
                const int k = lr[j];
                sbx += B[k * 3 + 0];  sby += B[k * 3 + 1];  sbz += B[k * 3 + 2];
                spx += Pr[k * 3 + 0]; spy += Pr[k * 3 + 1]; spz += Pr[k * 3 + 2];
            }
            const float bx = B[p * 3 + 0],  by = B[p * 3 + 1],  bz = B[p * 3 + 2];
            const float px = Pr[p * 3 + 0], py = Pr[p * 3 + 1], pz = Pr[p * 3 + 2];
            const float mvx = bx - px, mvy = by - py, mvz = bz - pz;
            const float dx = mvx - (sbx - spx) * invc;
            const float dy = mvy - (sby - spy) * invc;
            const float dz = mvz - (sbz - spz) * invc;
            sl = dx * dx + dy * dy + dz * dz;
            sm = mvx * mvx + mvy * mvy + mvz * mvz;
        }
        const unsigned m = 0xffffffffu;
        const int s0 = __shfl_sync(m, lvl, 0);
        if (__all_sync(m, lvl == s0)) {
            const float a = warpSum(sl);
            const float b = warpSum(sm);
            if ((tix & 31) == 0 && s0 >= 0) {
                atomicAdd(&g_acc[12 + s0], a);
                atomicAdd(&g_acc[15 + s0], b);
            }
        } else if (lvl >= 0) {
            atomicAdd(&g_acc[12 + lvl], sl);
            atomicAdd(&g_acc[15 + lvl], sm);
        }
    } else {
        // ----- bce (grid-stride over images) -----
        const int N = NB * 3 * 224 * 224;
        const int stride = 192 * 256;
        float s = 0.f;
        for (int k = (bid - 771) * 256 + tix; k < N; k += stride) {
            const float g = gt_img[k];
            const float rv = reconst[k];
            s += g * __logf(rv) + (1.f - g) * __logf(1.f - rv);
        }
        s = warpSum(s);
        if ((tix & 31) == 0) atomicAdd(&g_acc[18], s);
    }
}

// ---------------------------------------------------------------------------
// Post kernel: [0,207) scratch reduce (52960 entries), [207,359) edge+normal.
// ---------------------------------------------------------------------------
__global__ void __launch_bounds__(256) post_kernel(
    const float* __restrict__ p0, const float* __restrict__ p1, const float* __restrict__ p2,
    const int* __restrict__ e0, const int* __restrict__ e1, const int* __restrict__ e2,
    const float* __restrict__ gtn) {
    const int bid = blockIdx.x;
    const int tix = threadIdx.x;
    if (bid < 207) {
        const int j = bid * 256 + tix;
        float val = 0.f;
        int slot = -1;
        if (j < 3240) {
            slot = (j < 156) ? 0 : (j < 774) ? 1 : 2;
            val = funkey((unsigned int)(g_min64[j] >> 32));
        } else if (j < 12960) {
            const int jj = j - 3240;
            slot = (jj < 468) ? 0 : (jj < 2322) ? 1 : 2;
            val = funkey(g_min32[jj]);
        } else if (j < 52960) {
            slot = 5;
            val = funkey(g_gp_min[j - 12960]);
        }
        const unsigned m = 0xffffffffu;
        const int s0 = __shfl_sync(m, slot, 0);
        if (__all_sync(m, slot == s0)) {
            const float s = warpSum(val);
            if ((tix & 31) == 0 && s0 >= 0) atomicAdd(&g_acc[s0], s);
        } else if (slot >= 0) {
            atomicAdd(&g_acc[slot], val);
        }
    } else {
        int i = (bid - 207) * 256 + tix;
        float se = 0.f, sn = 0.f;
        int lvl = -1;
        if (i < 38808) {
            int E, P, off;
            const float* pred; const int* edges;
            if (i < 1848)      { lvl = 0; E = 462;  P = 156;  off = 0;   pred = p0; edges = e0; }
            else if (i < 9240) { lvl = 1; E = 1848; P = 618;  off = 156; pred = p1; edges = e1; i -= 1848; }
            else               { lvl = 2; E = 7392; P = 2466; off = 774; pred = p2; edges = e2; i -= 9240; }
            const int e = i % E;
            const int n = i / E;
            const int a = edges[e * 2 + 0];
            const int b = edges[e * 2 + 1];
            const float* pa = pred + ((size_t)n * P + a) * 3;
            const float* pb = pred + ((size_t)n * P + b) * 3;
            const float dx = pa[0] - pb[0];
            const float dy = pa[1] - pb[1];
            const float dz = pa[2] - pb[2];
            const float l2 = dx * dx + dy * dy + dz * dz;
            se = l2;
            const float inv_e = 1.f / fmaxf(sqrtf(l2), 1e-12f);
            const int gi = (int)(g_min64[off + a] & 0xFFFFFFFFull);
            const float* nr = gtn + ((size_t)n * QN + gi) * 3;
            const float nx = nr[0], ny = nr[1], nz = nr[2];
            const float inv_n = 1.f / fmaxf(sqrtf(nx * nx + ny * ny + nz * nz), 1e-12f);
            sn = fabsf((dx * nx + dy * ny + dz * nz) * inv_e * inv_n);
        }
        const unsigned m = 0xffffffffu;
        const int s0 = __shfl_sync(m, lvl, 0);
        if (__all_sync(m, lvl == s0)) {
            const float a = warpSum(se);
            const float b = warpSum(sn);
            if ((tix & 31) == 0 && s0 >= 0) {
                atomicAdd(&g_acc[6 + s0], a);
                atomicAdd(&g_acc[9 + s0], b);
            }
        } else if (lvl >= 0) {
            atomicAdd(&g_acc[6 + lvl], se);
            atomicAdd(&g_acc[9 + lvl], sn);
        }
    }
}

// ---------------------------------------------------------------------------
__global__ void finalize_kernel(float* out) {
    if (threadIdx.x != 0 || blockIdx.x != 0) return;
    const float Pl[3] = {156.f, 618.f, 2466.f};
    const float El[3] = {462.f, 1848.f, 7392.f};
    const float lapc[3] = {0.2f, 1.f, 1.f};
    float chamfer = 0.f, edge = 0.f, nrm = 0.f, lap = 0.f, mov = 0.f;
    for (int i = 0; i < 3; i++) {
        chamfer += g_acc[i] / (4.f * Pl[i]) + 0.55f * (g_acc[3 + i] / (4.f * (float)QN));
        edge    += g_acc[6 + i]  / (4.f * El[i]);
        nrm     += g_acc[9 + i]  / (4.f * El[i]);
        lap     += lapc[i] * g_acc[12 + i] / (4.f * Pl[i]);
        if (i > 0) mov += lapc[i] * g_acc[15 + i] / (4.f * Pl[i]);
    }
    const float img = -g_acc[18] / (4.f * 3.f * 224.f * 224.f);
    out[0] = chamfer + 1.0f * img + 0.5f * lap + 0.1f * mov + 0.1f * edge + 0.00016f * nrm;
}

// ---------------------------------------------------------------------------
// Inputs classified BY ELEMENT COUNT (robust to metadata ordering).
// ---------------------------------------------------------------------------
extern "C" void kernel_launch(void* const* d_in, const int* in_sizes, int n_in,
                              void* d_out, int out_size) {
    const int szCoord[3] = {NB * 156 * 3, NB * 618 * 3, NB * 2466 * 3};
    const int szEdge[3]  = {462 * 2, 1848 * 2, 7392 * 2};
    const int szLap[3]   = {156 * 10, 618 * 10, 2466 * 10};
    const int szGt  = NB * QN * 3;
    const int szImg = NB * 3 * 224 * 224;

    const float* pred[3]   = {0, 0, 0};
    const float* before[3] = {0, 0, 0};
    const int*   edges[3]  = {0, 0, 0};
    const int*   lap[3]    = {0, 0, 0};
    const float* gt_pts = 0; const float* gt_nrm = 0;
    const float* gt_img = 0; const float* reconst = 0;

    for (int i = 0; i < n_in; i++) {
        const int s = in_sizes[i];
        bool done = false;
        for (int l = 0; l < 3 && !done; l++) {
            if (s == szCoord[l]) {
                if (!pred[l]) pred[l] = (const float*)d_in[i];
                else          before[l] = (const float*)d_in[i];
                done = true;
            } else if (s == szEdge[l]) {
                edges[l] = (const int*)d_in[i]; done = true;
            } else if (s == szLap[l]) {
                lap[l] = (const int*)d_in[i]; done = true;
            }
        }
        if (done) continue;
        if (s == szGt) {
            if (!gt_pts) gt_pts = (const float*)d_in[i];
            else         gt_nrm = (const float*)d_in[i];
        } else if (s == szImg) {
            if (!gt_img) gt_img = (const float*)d_in[i];
            else         reconst = (const float*)d_in[i];
        }
    }

    float* out = (float*)d_out;

    init_kernel<<<157, 256>>>();
    main_kernel<<<963, 256>>>(pred[0], pred[1], pred[2],
                              before[0], before[1], before[2],
                              lap[0], lap[1], lap[2],
                              gt_pts, gt_img, reconst);
    post_kernel<<<359, 256>>>(pred[0], pred[1], pred[2],
                              edges[0], edges[1], edges[2], gt_nrm);
    finalize_kernel<<<1, 32>>>(out);
}

// round 13
// speedup vs baseline: 1.7082x; 1.7082x over previous
#include <cuda_runtime.h>
#include <math.h>

#define NB 4
#define QN 10000

// g_acc slots: 0..2 pg, 3..5 gp, 6..8 edge, 9..11 normal, 12..14 lap,
//              15..17 move, 18 bce
__device__ float g_acc[20];
__device__ unsigned int       g_min32[9720];   // pg mins, n>0: lvl bases {0,468,2322}, idx (n-1)*P+p
__device__ unsigned long long g_min64[3240];   // pg batch-0: (key<<32)|gt_idx, lvl bases {0,156,774}
__device__ unsigned int       g_gp_min[40000]; // gp lvl2 mins: n*QN + q

__device__ __forceinline__ unsigned int fkey(float f) {
    unsigned int u = __float_as_uint(f);
    return (u & 0x80000000u) ? ~u : (u | 0x80000000u);
}
__device__ __forceinline__ float funkey(unsigned int k) {
    unsigned int u = (k & 0x80000000u) ? (k ^ 0x80000000u) : ~k;
    return __uint_as_float(u);
}
__device__ __forceinline__ float warpSum(float v) {
    #pragma unroll
    for (int o = 16; o > 0; o >>= 1) v += __shfl_down_sync(0xffffffffu, v, o);
    return v;
}

// ---------------------------------------------------------------------------
__global__ void init_kernel() {
    const int i = blockIdx.x * blockDim.x + threadIdx.x;
    if (i < 20) g_acc[i] = 0.0f;
    if (i < 9720) g_min32[i] = 0xFFFFFFFFu;
    if (i < 3240) g_min64[i] = 0xFFFFFFFFFFFFFFFFull;
    if (i < 40000) g_gp_min[i] = 0xFFFFFFFFu;
}

// ---------------------------------------------------------------------------
// Main kernel (256 threads). Block roles:
//   [0,560)     pg  (lvl0 [0,40), lvl1 [40,160), lvl2 [160,560))
//               per lvl: r -> gc = r%10, n = (r/10)%4, pc = r/40
//   [560,1360)  gp  (lvl0 [0,160), lvl1 [160,320), lvl2 [320,800) of r=bid-560)
//               lvl0/1: full level in one chunk, direct warpSum+atomicAdd
//               lvl2:   3 chunks of 822, atomicMin scratch
//   [1360,1411) lap+move
//   [1411,1603) bce (grid-stride)
// Inner loops track min of (|pt|^2 - 2*dot); the thread's own |x|^2 is added
// once at the end (monotone shift — same min/argmin).
// ---------------------------------------------------------------------------
__global__ void __launch_bounds__(256) main_kernel(
    const float* __restrict__ p0, const float* __restrict__ p1, const float* __restrict__ p2,
    const float* __restrict__ be0, const float* __restrict__ be1, const float* __restrict__ be2,
    const int* __restrict__ l0, const int* __restrict__ l1, const int* __restrict__ l2i,
    const float* __restrict__ gt,
    const float* __restrict__ gt_img, const float* __restrict__ reconst) {
    __shared__ float4 sq[1000];
    const int bid = blockIdx.x;
    const int tix = threadIdx.x;

    if (bid < 560) {
        // ----- pg: per pred point, min over a 1000-pt GT chunk -----
        int r, P, lvl;
        const float* pred;
        if (bid < 40)       { lvl = 0; r = bid;       P = 156;  pred = p0; }
        else if (bid < 160) { lvl = 1; r = bid - 40;  P = 618;  pred = p1; }
        else                { lvl = 2; r = bid - 160; P = 2466; pred = p2; }
        const int gc = r % 10;
        const int n  = (r / 10) % NB;
        const int pc = r / 40;
        const int p  = pc * 256 + tix;
        const int base32[3] = {0, 468, 2322};
        const int base64[3] = {0, 156, 774};

        const float* g = gt + ((size_t)n * QN + gc * 1000) * 3;
        for (int t = tix; t < 1000; t += 256) {
            const float qx = g[3 * t + 0];
            const float qy = g[3 * t + 1];
            const float qz = g[3 * t + 2];
            sq[t] = make_float4(qx, qy, qz, qx * qx + qy * qy + qz * qz);
        }
        __syncthreads();
        if (p >= P) return;

        const float* pp = pred + ((size_t)n * P + p) * 3;
        const float px = pp[0], py = pp[1], pz = pp[2];
        const float x2 = px * px + py * py + pz * pz;
        const float mx = -2.f * px, my = -2.f * py, mz = -2.f * pz;

        if (n == 0) {
            float b0 = 3.4e38f, b1 = 3.4e38f, b2 = 3.4e38f, b3 = 3.4e38f;
            int i0 = 0, i1 = 1, i2 = 2, i3 = 3;
            for (int t = 0; t < 1000; t += 4) {
                const float4 q0 = sq[t + 0];
                const float4 q1 = sq[t + 1];
                const float4 q2 = sq[t + 2];
                const float4 q3 = sq[t + 3];
                const float d0 = fmaf(mx, q0.x, fmaf(my, q0.y, fmaf(mz, q0.z, q0.w)));
                const float d1 = fmaf(mx, q1.x, fmaf(my, q1.y, fmaf(mz, q1.z, q1.w)));
                const float d2 = fmaf(mx, q2.x, fmaf(my, q2.y, fmaf(mz, q2.z, q2.w)));
                const float d3 = fmaf(mx, q3.x, fmaf(my, q3.y, fmaf(mz, q3.z, q3.w)));
                if (d0 < b0) { b0 = d0; i0 = t + 0; }
                if (d1 < b1) { b1 = d1; i1 = t + 1; }
                if (d2 < b2) { b2 = d2; i2 = t + 2; }
                if (d3 < b3) { b3 = d3; i3 = t + 3; }
            }
            float best = b0; int bi = i0;
            if (b1 < best || (b1 == best && i1 < bi)) { best = b1; bi = i1; }
            if (b2 < best || (b2 == best && i2 < bi)) { best = b2; bi = i2; }
            if (b3 < best || (b3 == best && i3 < bi)) { best = b3; bi = i3; }
            const unsigned int key = fkey(x2 + best);
            atomicMin(&g_min64[base64[lvl] + p],
                      ((unsigned long long)key << 32) | (unsigned int)(gc * 1000 + bi));
        } else {
            float b0 = 3.4e38f, b1 = 3.4e38f, b2 = 3.4e38f, b3 = 3.4e38f;
            for (int t = 0; t < 1000; t += 4) {
                const float4 q0 = sq[t + 0];
                const float4 q1 = sq[t + 1];
                const float4 q2 = sq[t + 2];
                const float4 q3 = sq[t + 3];
                b0 = fminf(b0, fmaf(mx, q0.x, fmaf(my, q0.y, fmaf(mz, q0.z, q0.w))));
                b1 = fminf(b1, fmaf(mx, q1.x, fmaf(my, q1.y, fmaf(mz, q1.z, q1.w))));
                b2 = fminf(b2, fmaf(mx, q2.x, fmaf(my, q2.y, fmaf(mz, q2.z, q2.w))));
                b3 = fminf(b3, fmaf(mx, q3.x, fmaf(my, q3.y, fmaf(mz, q3.z, q3.w))));
            }
            const float best = x2 + fminf(fminf(b0, b1), fminf(b2, b3));
            atomicMin(&g_min32[base32[lvl] + (n - 1) * P + p], fkey(best));
        }
    } else if (bid < 1360) {
        // ----- gp: per GT point, min over pred chunk -----
        const int r = bid - 560;
        int lvl, rr;
        if (r < 160)      { lvl = 0; rr = r; }
        else if (r < 320) { lvl = 1; rr = r - 160; }
        else              { lvl = 2; rr = r - 320; }
        int P; const float* pred;
        if (lvl == 0)      { P = 156;  pred = p0; }
        else if (lvl == 1) { P = 618;  pred = p1; }
        else               { P = 2466; pred = p2; }
        const int qc = rr % 40;
        const int t2 = rr / 40;
        const int n  = t2 % NB;
        const int pc = t2 / NB;              // 0 for lvl0/1; 0..2 for lvl2
        const int start = pc * 822;
        const int cnt = (lvl == 2) ? 822 : P;   // full coverage: 3*822 = 2466

        const float* pr = pred + ((size_t)n * P + start) * 3;
        for (int t = tix; t < cnt; t += 256) {
            const float x = pr[3 * t + 0];
            const float y = pr[3 * t + 1];
            const float z = pr[3 * t + 2];
            sq[t] = make_float4(x, y, z, x * x + y * y + z * z);
        }
        __syncthreads();

        const int q = qc * 256 + tix;
        const bool valid = (q < QN);
        float best = 0.f;
        if (valid) {
            const float* gq = gt + ((size_t)n * QN + q) * 3;
            const float qx = gq[0], qy = gq[1], qz = gq[2];
            const float q2 = qx * qx + qy * qy + qz * qz;
            const float mx = -2.f * qx, my = -2.f * qy, mz = -2.f * qz;
            float b0 = 3.4e38f, b1 = 3.4e38f, b2 = 3.4e38f, b3 = 3.4e38f;
            int t = 0;
            for (; t + 4 <= cnt; t += 4) {
                const float4 v0 = sq[t + 0];
                const float4 v1 = sq[t + 1];
                const float4 v2 = sq[t + 2];
                const float4 v3 = sq[t + 3];
                b0 = fminf(b0, fmaf(mx, v0.x, fmaf(my, v0.y, fmaf(mz, v0.z, v0.w))));
                b1 = fminf(b1, fmaf(mx, v1.x, fmaf(my, v1.y, fmaf(mz, v1.z, v1.w))));
                b2 = fminf(b2, fmaf(mx, v2.x, fmaf(my, v2.y, fmaf(mz, v2.z, v2.w))));
                b3 = fminf(b3, fmaf(mx, v3.x, fmaf(my, v3.y, fmaf(mz, v3.z, v3.w))));
            }
            for (; t < cnt; t++) {
                const float4 v = sq[t];
                b0 = fminf(b0, fmaf(mx, v.x, fmaf(my, v.y, fmaf(mz, v.z, v.w))));
            }
            best = q2 + fminf(fminf(b0, b1), fminf(b2, b3));
        }
        if (lvl < 2) {
            // single chunk covers the whole level: sum directly
            const float s = warpSum(valid ? best : 0.f);
            if ((tix & 31) == 0) atomicAdd(&g_acc[3 + lvl], s);
        } else {
            if (valid) atomicMin(&g_gp_min[n * QN + q], fkey(best));
        }
    } else if (bid < 1411) {
        // ----- laplace + move -----
        int i = (bid - 1360) * 256 + tix;
        float sl = 0.f, sm = 0.f;
        int lvl = -1;
        if (i < 12960) {
            int P; const float* pred; const float* bef; const int* lap;
            if (i < 624)       { lvl = 0; P = 156;  pred = p0; bef = be0; lap = l0; }
            else if (i < 3096) { lvl = 1; P = 618;  pred = p1; bef = be1; lap = l1; i -= 624; }
            else               { lvl = 2; P = 2466; pred = p2; bef = be2; lap = l2i; i -= 3096; }
            const int p = i % P;
            const int n = i / P;
            const int* lr = lap + (size_t)p * 10;
            const float invc = 1.f / (float)lr[9];
            const float* B  = bef  + (size_t)n * P * 3;
            const float* Pr = pred + (size_t)n * P * 3;
            float sbx = 0.f, sby = 0.f, sbz = 0.f;
            float spx = 0.f, spy = 0.f, spz = 0.f;
            #pragma unroll
            for (int j = 0; j < 8; j++) {
                const int k = lr[j];
                sbx += B[k * 3 + 0];  sby += B[k * 3 + 1];  sbz += B[k * 3 + 2];
                spx += Pr[k * 3 + 0]; spy += Pr[k * 3 + 1]; spz += Pr[k * 3 + 2];
            }
            const float bx = B[p * 3 + 0],  by = B[p * 3 + 1],  bz = B[p * 3 + 2];
            const float px = Pr[p * 3 + 0], py = Pr[p * 3 + 1], pz = Pr[p * 3 + 2];
            const float mvx = bx - px, mvy = by - py, mvz = bz - pz;
            const float dx = mvx - (sbx - spx) * invc;
            const float dy = mvy - (sby - spy) * invc;
            const float dz = mvz - (sbz - spz) * invc;
            sl = dx * dx + dy * dy + dz * dz;
            sm = mvx * mvx + mvy * mvy + mvz * mvz;
        }
        const unsigned m = 0xffffffffu;
        const int s0 = __shfl_sync(m, lvl, 0);
        if (__all_sync(m, lvl == s0)) {
            const float a = warpSum(sl);
            const float b = warpSum(sm);
            if ((tix & 31) == 0 && s0 >= 0) {
                atomicAdd(&g_acc[12 + s0], a);
                atomicAdd(&g_acc[15 + s0], b);
            }
        } else if (lvl >= 0) {
            atomicAdd(&g_acc[12 + lvl], sl);
            atomicAdd(&g_acc[15 + lvl], sm);
        }
    } else {
        // ----- bce (grid-stride over images) -----
        const int N = NB * 3 * 224 * 224;
        const int stride = 192 * 256;
        float s = 0.f;
        for (int k = (bid - 1411) * 256 + tix; k < N; k += stride) {
            const float g = gt_img[k];
            const float rv = reconst[k];
            s += g * __logf(rv) + (1.f - g) * __logf(1.f - rv);
        }
        s = warpSum(s);
        if ((tix & 31) == 0) atomicAdd(&g_acc[18], s);
    }
}

// ---------------------------------------------------------------------------
// Post kernel: [0,207) scratch reduce (52960 entries), [207,359) edge+normal.
// ---------------------------------------------------------------------------
__global__ void __launch_bounds__(256) post_kernel(
    const float* __restrict__ p0, const float* __restrict__ p1, const float* __restrict__ p2,
    const int* __restrict__ e0, const int* __restrict__ e1, const int* __restrict__ e2,
    const float* __restrict__ gtn) {
    const int bid = blockIdx.x;
    const int tix = threadIdx.x;
    if (bid < 207) {
        const int j = bid * 256 + tix;
        float val = 0.f;
        int slot = -1;
        if (j < 3240) {
            slot = (j < 156) ? 0 : (j < 774) ? 1 : 2;
            val = funkey((unsigned int)(g_min64[j] >> 32));
        } else if (j < 12960) {
            const int jj = j - 3240;
            slot = (jj < 468) ? 0 : (jj < 2322) ? 1 : 2;
            val = funkey(g_min32[jj]);
        } else if (j < 52960) {
            slot = 5;
            val = funkey(g_gp_min[j - 12960]);
        }
        const unsigned m = 0xffffffffu;
        const int s0 = __shfl_sync(m, slot, 0);
        if (__all_sync(m, slot == s0)) {
            const float s = warpSum(val);
            if ((tix & 31) == 0 && s0 >= 0) atomicAdd(&g_acc[s0], s);
        } else if (slot >= 0) {
            atomicAdd(&g_acc[slot], val);
        }
    } else {
        int i = (bid - 207) * 256 + tix;
        float se = 0.f, sn = 0.f;
        int lvl = -1;
        if (i < 38808) {
            int E, P, off;
            const float* pred; const int* edges;
            if (i < 1848)      { lvl = 0; E = 462;  P = 156;  off = 0;   pred = p0; edges = e0; }
            else if (i < 9240) { lvl = 1; E = 1848; P = 618;  off = 156; pred = p1; edges = e1; i -= 1848; }
            else               { lvl = 2; E = 7392; P = 2466; off = 774; pred = p2; edges = e2; i -= 9240; }
            const int e = i % E;
            const int n = i / E;
            const int a = edges[e * 2 + 0];
            const int b = edges[e * 2 + 1];
            const float* pa = pred + ((size_t)n * P + a) * 3;
            const float* pb = pred + ((size_t)n * P + b) * 3;
            const float dx = pa[0] - pb[0];
            const float dy = pa[1] - pb[1];
            const float dz = pa[2] - pb[2];
            const float l2 = dx * dx + dy * dy + dz * dz;
            se = l2;
            const float inv_e = 1.f / fmaxf(sqrtf(l2), 1e-12f);
            const int gi = (int)(g_min64[off + a] & 0xFFFFFFFFull);
            const float* nr = gtn + ((size_t)n * QN + gi) * 3;
            const float nx = nr[0], ny = nr[1], nz = nr[2];
            const float inv_n = 1.f / fmaxf(sqrtf(nx * nx + ny * ny + nz * nz), 1e-12f);
            sn = fabsf((dx * nx + dy * ny + dz * nz) * inv_e * inv_n);
        }
        const unsigned m = 0xffffffffu;
        const int s0 = __shfl_sync(m, lvl, 0);
        if (__all_sync(m, lvl == s0)) {
            const float a = warpSum(se);
            const float b = warpSum(sn);
            if ((tix & 31) == 0 && s0 >= 0) {
                atomicAdd(&g_acc[6 + s0], a);
                atomicAdd(&g_acc[9 + s0], b);
            }
        } else if (lvl >= 0) {
            atomicAdd(&g_acc[6 + lvl], se);
            atomicAdd(&g_acc[9 + lvl], sn);
        }
    }
}

// ---------------------------------------------------------------------------
__global__ void finalize_kernel(float* out) {
    if (threadIdx.x != 0 || blockIdx.x != 0) return;
    const float Pl[3] = {156.f, 618.f, 2466.f};
    const float El[3] = {462.f, 1848.f, 7392.f};
    const float lapc[3] = {0.2f, 1.f, 1.f};
    float chamfer = 0.f, edge = 0.f, nrm = 0.f, lap = 0.f, mov = 0.f;
    for (int i = 0; i < 3; i++) {
        chamfer += g_acc[i] / (4.f * Pl[i]) + 0.55f * (g_acc[3 + i] / (4.f * (float)QN));
        edge    += g_acc[6 + i]  / (4.f * El[i]);
        nrm     += g_acc[9 + i]  / (4.f * El[i]);
        lap     += lapc[i] * g_acc[12 + i] / (4.f * Pl[i]);
        if (i > 0) mov += lapc[i] * g_acc[15 + i] / (4.f * Pl[i]);
    }
    const float img = -g_acc[18] / (4.f * 3.f * 224.f * 224.f);
    out[0] = chamfer + 1.0f * img + 0.5f * lap + 0.1f * mov + 0.1f * edge + 0.00016f * nrm;
}

// ---------------------------------------------------------------------------
// Inputs classified BY ELEMENT COUNT (robust to metadata ordering).
// ---------------------------------------------------------------------------
extern "C" void kernel_launch(void* const* d_in, const int* in_sizes, int n_in,
                              void* d_out, int out_size) {
    const int szCoord[3] = {NB * 156 * 3, NB * 618 * 3, NB * 2466 * 3};
    const int szEdge[3]  = {462 * 2, 1848 * 2, 7392 * 2};
    const int szLap[3]   = {156 * 10, 618 * 10, 2466 * 10};
    const int szGt  = NB * QN * 3;
    const int szImg = NB * 3 * 224 * 224;

    const float* pred[3]   = {0, 0, 0};
    const float* before[3] = {0, 0, 0};
    const int*   edges[3]  = {0, 0, 0};
    const int*   lap[3]    = {0, 0, 0};
    const float* gt_pts = 0; const float* gt_nrm = 0;
    const float* gt_img = 0; const float* reconst = 0;

    for (int i = 0; i < n_in; i++) {
        const int s = in_sizes[i];
        bool done = false;
        for (int l = 0; l < 3 && !done; l++) {
            if (s == szCoord[l]) {
                if (!pred[l]) pred[l] = (const float*)d_in[i];
                else          before[l] = (const float*)d_in[i];
                done = true;
            } else if (s == szEdge[l]) {
                edges[l] = (const int*)d_in[i]; done = true;
            } else if (s == szLap[l]) {
                lap[l] = (const int*)d_in[i]; done = true;
            }
        }
        if (done) continue;
        if (s == szGt) {
            if (!gt_pts) gt_pts = (const float*)d_in[i];
            else         gt_nrm = (const float*)d_in[i];
        } else if (s == szImg) {
            if (!gt_img) gt_img = (const float*)d_in[i];
            else         reconst = (const float*)d_in[i];
        }
    }

    float* out = (float*)d_out;

    init_kernel<<<157, 256>>>();
    main_kernel<<<1603, 256>>>(pred[0], pred[1], pred[2],
                               before[0], before[1], before[2],
                               lap[0], lap[1], lap[2],
                               gt_pts, gt_img, reconst);
    post_kernel<<<359, 256>>>(pred[0], pred[1], pred[2],
                              edges[0], edges[1], edges[2], gt_nrm);
    finalize_kernel<<<1, 32>>>(out);
}

// round 15
// speedup vs baseline: 1.8059x; 1.0572x over previous
#include <cuda_runtime.h>
#include <math.h>

#define NB 4
#define QN 10000

// g_acc slots: 0..2 pg, 3..5 gp, 6..8 edge, 9..11 normal, 12..14 lap,
//              15..17 move, 18 bce
__device__ float g_acc[20];
__device__ unsigned int       g_min32[9720];   // pg mins, n>0: lvl bases {0,468,2322}, idx (n-1)*P+p
__device__ unsigned long long g_min64[3240];   // pg batch-0: (key<<32)|gt_idx, lvl bases {0,156,774}
__device__ unsigned int       g_gp_min[40000]; // gp lvl2 mins: n*QN + q

__device__ __forceinline__ unsigned int fkey(float f) {
    unsigned int u = __float_as_uint(f);
    return (u & 0x80000000u) ? ~u : (u | 0x80000000u);
}
__device__ __forceinline__ float funkey(unsigned int k) {
    unsigned int u = (k & 0x80000000u) ? (k ^ 0x80000000u) : ~k;
    return __uint_as_float(u);
}
__device__ __forceinline__ float warpSum(float v) {
    #pragma unroll
    for (int o = 16; o > 0; o >>= 1) v += __shfl_down_sync(0xffffffffu, v, o);
    return v;
}

// ---- packed f32x2 FMA (FFMA2 — PTX only) ----------------------------------
union U64F2 { unsigned long long u; float2 f; };
__device__ __forceinline__ unsigned long long packf2(float x, float y) {
    U64F2 t; t.f.x = x; t.f.y = y; return t.u;
}
__device__ __forceinline__ float2 ffma2(unsigned long long a, unsigned long long b,
                                        unsigned long long c) {
    U64F2 d;
    asm("fma.rn.f32x2 %0, %1, %2, %3;" : "=l"(d.u) : "l"(a), "l"(b), "l"(c));
    return d.f;
}

// Packed tile loader: from 2 consecutive points (6 floats) build
// sA[t]=(x0,x1,y0,y1), sB[t]=(z0,z1,w0,w1), w = |pt|^2.
// src must point at an even point index; 'pairs' entries are written.
__device__ __forceinline__ void load_packed_tile(float4* sA, float4* sB,
                                                 const float* __restrict__ src,
                                                 int pairs, int tix) {
    for (int t = tix; t < pairs; t += 256) {
        const float2 v0 = *(const float2*)(src + 6 * t);       // x0 y0
        const float2 v1 = *(const float2*)(src + 6 * t + 2);   // z0 x1
        const float2 v2 = *(const float2*)(src + 6 * t + 4);   // y1 z1
        const float w0 = v0.x * v0.x + v0.y * v0.y + v1.x * v1.x;
        const float w1 = v1.y * v1.y + v2.x * v2.x + v2.y * v2.y;
        sA[t] = make_float4(v0.x, v1.y, v0.y, v2.x);
        sB[t] = make_float4(v1.x, v2.y, w0, w1);
    }
}

// Packed min scan over 'pairs' tile entries (2 points each), tracking min of
// (|pt|^2 - 2*dot). 4 independent min chains.
__device__ __forceinline__ float packed_min_scan(const float4* sA, const float4* sB,
                                                 int pairs,
                                                 unsigned long long mx2,
                                                 unsigned long long my2,
                                                 unsigned long long mz2) {
    float b0 = 3.4e38f, b1 = 3.4e38f, b2 = 3.4e38f, b3 = 3.4e38f;
    int t = 0;
    for (; t + 2 <= pairs; t += 2) {
        const float4 A0 = sA[t],     B0 = sB[t];
        const float4 A1 = sA[t + 1], B1 = sB[t + 1];
        float2 e0 = ffma2(mz2, packf2(B0.x, B0.y), packf2(B0.z, B0.w));
        float2 e1 = ffma2(mz2, packf2(B1.x, B1.y), packf2(B1.z, B1.w));
        e0 = ffma2(my2, packf2(A0.z, A0.w), packf2(e0.x, e0.y));
        e1 = ffma2(my2, packf2(A1.z, A1.w), packf2(e1.x, e1.y));
        e0 = ffma2(mx2, packf2(A0.x, A0.y), packf2(e0.x, e0.y));
        e1 = ffma2(mx2, packf2(A1.x, A1.y), packf2(e1.x, e1.y));
        b0 = fminf(b0, e0.x); b1 = fminf(b1, e0.y);
        b2 = fminf(b2, e1.x); b3 = fminf(b3, e1.y);
    }
    if (t < pairs) {
        const float4 A0 = sA[t], B0 = sB[t];
        float2 e0 = ffma2(mz2, packf2(B0.x, B0.y), packf2(B0.z, B0.w));
        e0 = ffma2(my2, packf2(A0.z, A0.w), packf2(e0.x, e0.y));
        e0 = ffma2(mx2, packf2(A0.x, A0.y), packf2(e0.x, e0.y));
        b0 = fminf(b0, e0.x); b1 = fminf(b1, e0.y);
    }
    return fminf(fminf(b0, b1), fminf(b2, b3));
}

// ---------------------------------------------------------------------------
__global__ void init_kernel() {
    const int i = blockIdx.x * blockDim.x + threadIdx.x;
    if (i < 20) g_acc[i] = 0.0f;
    if (i < 9720) g_min32[i] = 0xFFFFFFFFu;
    if (i < 3240) g_min64[i] = 0xFFFFFFFFFFFFFFFFull;
    if (i < 40000) g_gp_min[i] = 0xFFFFFFFFu;
}

// ---------------------------------------------------------------------------
// Main kernel (256 threads). Block roles identical to the 82.8us config:
//   [0,560)     pg  (lvl0 [0,40), lvl1 [40,160), lvl2 [160,560)); 1000-pt GT chunks
//   [560,1360)  gp  (lvl0/1 full level one chunk direct-sum; lvl2 3x822 scratch)
//   [1360,1411) lap+move
//   [1411,1603) bce
// Min-only chamfer bodies use packed FFMA2; pg batch-0 argmin stays scalar.
// ---------------------------------------------------------------------------
__global__ void __launch_bounds__(256) main_kernel(
    const float* __restrict__ p0, const float* __restrict__ p1, const float* __restrict__ p2,
    const float* __restrict__ be0, const float* __restrict__ be1, const float* __restrict__ be2,
    const int* __restrict__ l0, const int* __restrict__ l1, const int* __restrict__ l2i,
    const float* __restrict__ gt,
    const float* __restrict__ gt_img, const float* __restrict__ reconst) {
    __shared__ float4 s_buf[1000];
    float4* sA = s_buf;
    float4* sB = s_buf + 500;
    const int bid = blockIdx.x;
    const int tix = threadIdx.x;

    if (bid < 560) {
        // ----- pg: per pred point, min over a 1000-pt GT chunk (500 pairs) -----
        int r, P, lvl;
        const float* pred;
        if (bid < 40)       { lvl = 0; r = bid;       P = 156;  pred = p0; }
        else if (bid < 160) { lvl = 1; r = bid - 40;  P = 618;  pred = p1; }
        else                { lvl = 2; r = bid - 160; P = 2466; pred = p2; }
        const int gc = r % 10;
        const int n  = (r / 10) % NB;
        const int pc = r / 40;
        const int p  = pc * 256 + tix;
        const int base32[3] = {0, 468, 2322};
        const int base64[3] = {0, 156, 774};

        const float* g = gt + ((size_t)n * QN + gc * 1000) * 3;
        load_packed_tile(sA, sB, g, 500, tix);
        __syncthreads();
        if (p >= P) return;

        const float* pp = pred + ((size_t)n * P + p) * 3;
        const float px = pp[0], py = pp[1], pz = pp[2];
        const float x2 = px * px + py * py + pz * pz;
        const float mx = -2.f * px, my = -2.f * py, mz = -2.f * pz;

        if (n == 0) {
            // argmin path: scalar on the packed tile (2 pts per entry, 2 chains)
            float b0 = 3.4e38f, b1 = 3.4e38f;
            int i0 = 0, i1 = 1;
            for (int t = 0; t < 500; t++) {
                const float4 A = sA[t], B = sB[t];
                const float d0 = fmaf(mx, A.x, fmaf(my, A.z, fmaf(mz, B.x, B.z)));
                const float d1 = fmaf(mx, A.y, fmaf(my, A.w, fmaf(mz, B.y, B.w)));
                if (d0 < b0) { b0 = d0; i0 = 2 * t; }
                if (d1 < b1) { b1 = d1; i1 = 2 * t + 1; }
            }
            float best; int bi;
            if (b0 < b1 || (b0 == b1 && i0 < i1)) { best = b0; bi = i0; }
            else                                   { best = b1; bi = i1; }
            const unsigned int key = fkey(x2 + best);
            atomicMin(&g_min64[base64[lvl] + p],
                      ((unsigned long long)key << 32) | (unsigned int)(gc * 1000 + bi));
        } else {
            const unsigned long long mx2 = packf2(mx, mx);
            const unsigned long long my2 = packf2(my, my);
            const unsigned long long mz2 = packf2(mz, mz);
            const float best = x2 + packed_min_scan(sA, sB, 500, mx2, my2, mz2);
            atomicMin(&g_min32[base32[lvl] + (n - 1) * P + p], fkey(best));
        }
    } else if (bid < 1360) {
        // ----- gp: per GT point, min over pred chunk (packed FFMA2) -----
        const int r = bid - 560;
        int lvl, rr;
        if (r < 160)      { lvl = 0; rr = r; }
        else if (r < 320) { lvl = 1; rr = r - 160; }
        else              { lvl = 2; rr = r - 320; }
        int P; const float* pred;
        if (lvl == 0)      { P = 156;  pred = p0; }
        else if (lvl == 1) { P = 618;  pred = p1; }
        else               { P = 2466; pred = p2; }
        const int qc = rr % 40;
        const int t2 = rr / 40;
        const int n  = t2 % NB;
        const int pc = t2 / NB;              // 0 for lvl0/1; 0..2 for lvl2
        const int start = pc * 822;
        const int cnt = (lvl == 2) ? 822 : P;   // 822/156/618 — all even
        const int pairs = cnt / 2;

        const float* pr = pred + ((size_t)n * P + start) * 3;
        load_packed_tile(sA, sB, pr, pairs, tix);
        __syncthreads();

        const int q = qc * 256 + tix;
        const bool valid = (q < QN);
        float best = 0.f;
        if (valid) {
            const float* gq = gt + ((size_t)n * QN + q) * 3;
            const float qx = gq[0], qy = gq[1], qz = gq[2];
            const float q2 = qx * qx + qy * qy + qz * qz;
            const unsigned long long mx2 = packf2(-2.f * qx, -2.f * qx);
            const unsigned long long my2 = packf2(-2.f * qy, -2.f * qy);
            const unsigned long long mz2 = packf2(-2.f * qz, -2.f * qz);
            best = q2 + packed_min_scan(sA, sB, pairs, mx2, my2, mz2);
        }
        if (lvl < 2) {
            const float s = warpSum(valid ? best : 0.f);
            if ((tix & 31) == 0) atomicAdd(&g_acc[3 + lvl], s);
        } else {
            if (valid) atomicMin(&g_gp_min[n * QN + q], fkey(best));
        }
    } else if (bid < 1411) {
        // ----- laplace + move -----
        int i = (bid - 1360) * 256 + tix;
        float sl = 0.f, sm = 0.f;
        int lvl = -1;
        if (i < 12960) {
            int P; const float* pred; const float* bef; const int* lap;
            if (i < 624)       { lvl = 0; P = 156;  pred = p0; bef = be0; lap = l0; }
            else if (i < 3096) { lvl = 1; P = 618;  pred = p1; bef = be1; lap = l1; i -= 624; }
            else               { lvl = 2; P = 2466; pred = p2; bef = be2; lap = l2i; i -= 3096; }
            const int p = i % P;
            const int n = i / P;
            const int* lr = lap + (size_t)p * 10;
            const float invc = 1.f / (float)lr[9];
            const float* B  = bef  + (size_t)n * P * 3;
            const float* Pr = pred + (size_t)n * P * 3;
            float sbx = 0.f, sby = 0.f, sbz = 0.f;
            float spx = 0.f, spy = 0.f, spz = 0.f;
            #pragma unroll
            for (int j = 0; j < 8; j++) {
                const int k = lr[j];
                sbx += B[k * 3 + 0];  sby += B[k * 3 + 1];  sbz += B[k * 3 + 2];
                spx += Pr[k * 3 + 0]; spy += Pr[k * 3 + 1]; spz += Pr[k * 3 + 2];
            }
            const float bx = B[p * 3 + 0],  by = B[p * 3 + 1],  bz = B[p * 3 + 2];
            const float px = Pr[p * 3 + 0], py = Pr[p * 3 + 1], pz = Pr[p * 3 + 2];
            const float mvx = bx - px, mvy = by - py, mvz = bz - pz;
            const float dx = mvx - (sbx - spx) * invc;
            const float dy = mvy - (sby - spy) * invc;
            const float dz = mvz - (sbz - spz) * invc;
            sl = dx * dx + dy * dy + dz * dz;
            sm = mvx * mvx + mvy * mvy + mvz * mvz;
        }
        const unsigned m = 0xffffffffu;
        const int s0 = __shfl_sync(m, lvl, 0);
        if (__all_sync(m, lvl == s0)) {
            const float a = warpSum(sl);
            const float b = warpSum(sm);
            if ((tix & 31) == 0 && s0 >= 0) {
                atomicAdd(&g_acc[12 + s0], a);
                atomicAdd(&g_acc[15 + s0], b);
            }
        } else if (lvl >= 0) {
            atomicAdd(&g_acc[12 + lvl], sl);
            atomicAdd(&g_acc[15 + lvl], sm);
        }
    } else {
        // ----- bce (grid-stride over images) -----
        const int N = NB * 3 * 224 * 224;
        const int stride = 192 * 256;
        float s = 0.f;
        for (int k = (bid - 1411) * 256 + tix; k < N; k += stride) {
            const float g = gt_img[k];
            const float rv = reconst[k];
            s += g * __logf(rv) + (1.f - g) * __logf(1.f - rv);
        }
        s = warpSum(s);
        if ((tix & 31) == 0) atomicAdd(&g_acc[18], s);
    }
}

// ---------------------------------------------------------------------------
// Post kernel: [0,207) scratch reduce (52960 entries), [207,359) edge+normal.
// ---------------------------------------------------------------------------
__global__ void __launch_bounds__(256) post_kernel(
    const float* __restrict__ p0, const float* __restrict__ p1, const float* __restrict__ p2,
    const int* __restrict__ e0, const int* __restrict__ e1, const int* __restrict__ e2,
    const float* __restrict__ gtn) {
    const int bid = blockIdx.x;
    const int tix = threadIdx.x;
    if (bid < 207) {
        const int j = bid * 256 + tix;
        float val = 0.f;
        int slot = -1;
        if (j < 3240) {
            slot = (j < 156) ? 0 : (j < 774) ? 1 : 2;
            val = funkey((unsigned int)(g_min64[j] >> 32));
        } else if (j < 12960) {
            const int jj = j - 3240;
            slot = (jj < 468) ? 0 : (jj < 2322) ? 1 : 2;
            val = funkey(g_min32[jj]);
        } else if (j < 52960) {
            slot = 5;
            val = funkey(g_gp_min[j - 12960]);
        }
        const unsigned m = 0xffffffffu;
        const int s0 = __shfl_sync(m, slot, 0);
        if (__all_sync(m, slot == s0)) {
            const float s = warpSum(val);
            if ((tix & 31) == 0 && s0 >= 0) atomicAdd(&g_acc[s0], s);
        } else if (slot >= 0) {
            atomicAdd(&g_acc[slot], val);
        }
    } else {
        int i = (bid - 207) * 256 + tix;
        float se = 0.f, sn = 0.f;
        int lvl = -1;
        if (i < 38808) {
            int E, P, off;
            const float* pred; const int* edges;
            if (i < 1848)      { lvl = 0; E = 462;  P = 156;  off = 0;   pred = p0; edges = e0; }
            else if (i < 9240) { lvl = 1; E = 1848; P = 618;  off = 156; pred = p1; edges = e1; i -= 1848; }
            else               { lvl = 2; E = 7392; P = 2466; off = 774; pred = p2; edges = e2; i -= 9240; }
            const int e = i % E;
            const int n = i / E;
            const int a = edges[e * 2 + 0];
            const int b = edges[e * 2 + 1];
            const float* pa = pred + ((size_t)n * P + a) * 3;
            const float* pb = pred + ((size_t)n * P + b) * 3;
            const float dx = pa[0] - pb[0];
            const float dy = pa[1] - pb[1];
            const float dz = pa[2] - pb[2];
            const float l2 = dx * dx + dy * dy + dz * dz;
            se = l2;
            const float inv_e = 1.f / fmaxf(sqrtf(l2), 1e-12f);
            const int gi = (int)(g_min64[off + a] & 0xFFFFFFFFull);
            const float* nr = gtn + ((size_t)n * QN + gi) * 3;
            const float nx = nr[0], ny = nr[1], nz = nr[2];
            const float inv_n = 1.f / fmaxf(sqrtf(nx * nx + ny * ny + nz * nz), 1e-12f);
            sn = fabsf((dx * nx + dy * ny + dz * nz) * inv_e * inv_n);
        }
        const unsigned m = 0xffffffffu;
        const int s0 = __shfl_sync(m, lvl, 0);
        if (__all_sync(m, lvl == s0)) {
            const float a = warpSum(se);
            const float b = warpSum(sn);
            if ((tix & 31) == 0 && s0 >= 0) {
                atomicAdd(&g_acc[6 + s0], a);
                atomicAdd(&g_acc[9 + s0], b);
            }
        } else if (lvl >= 0) {
            atomicAdd(&g_acc[6 + lvl], se);
            atomicAdd(&g_acc[9 + lvl], sn);
        }
    }
}

// ---------------------------------------------------------------------------
__global__ void finalize_kernel(float* out) {
    if (threadIdx.x != 0 || blockIdx.x != 0) return;
    const float Pl[3] = {156.f, 618.f, 2466.f};
    const float El[3] = {462.f, 1848.f, 7392.f};
    const float lapc[3] = {0.2f, 1.f, 1.f};
    float chamfer = 0.f, edge = 0.f, nrm = 0.f, lap = 0.f, mov = 0.f;
    for (int i = 0; i < 3; i++) {
        chamfer += g_acc[i] / (4.f * Pl[i]) + 0.55f * (g_acc[3 + i] / (4.f * (float)QN));
        edge    += g_acc[6 + i]  / (4.f * El[i]);
        nrm     += g_acc[9 + i]  / (4.f * El[i]);
        lap     += lapc[i] * g_acc[12 + i] / (4.f * Pl[i]);
        if (i > 0) mov += lapc[i] * g_acc[15 + i] / (4.f * Pl[i]);
    }
    const float img = -g_acc[18] / (4.f * 3.f * 224.f * 224.f);
    out[0] = chamfer + 1.0f * img + 0.5f * lap + 0.1f * mov + 0.1f * edge + 0.00016f * nrm;
}

// ---------------------------------------------------------------------------
// Inputs classified BY ELEMENT COUNT (robust to metadata ordering).
// ---------------------------------------------------------------------------
extern "C" void kernel_launch(void* const* d_in, const int* in_sizes, int n_in,
                              void* d_out, int out_size) {
    const int szCoord[3] = {NB * 156 * 3, NB * 618 * 3, NB * 2466 * 3};
    const int szEdge[3]  = {462 * 2, 1848 * 2, 7392 * 2};
    const int szLap[3]   = {156 * 10, 618 * 10, 2466 * 10};
    const int szGt  = NB * QN * 3;
    const int szImg = NB * 3 * 224 * 224;

    const float* pred[3]   = {0, 0, 0};
    const float* before[3] = {0, 0, 0};
    const int*   edges[3]  = {0, 0, 0};
    const int*   lap[3]    = {0, 0, 0};
    const float* gt_pts = 0; const float* gt_nrm = 0;
    const float* gt_img = 0; const float* reconst = 0;

    for (int i = 0; i < n_in; i++) {
        const int s = in_sizes[i];
        bool done = false;
        for (int l = 0; l < 3 && !done; l++) {
            if (s == szCoord[l]) {
                if (!pred[l]) pred[l] = (const float*)d_in[i];
                else          before[l] = (const float*)d_in[i];
                done = true;
            } else if (s == szEdge[l]) {
                edges[l] = (const int*)d_in[i]; done = true;
            } else if (s == szLap[l]) {
                lap[l] = (const int*)d_in[i]; done = true;
            }
        }
        if (done) continue;
        if (s == szGt) {
            if (!gt_pts) gt_pts = (const float*)d_in[i];
            else         gt_nrm = (const float*)d_in[i];
        } else if (s == szImg) {
            if (!gt_img) gt_img = (const float*)d_in[i];
            else         reconst = (const float*)d_in[i];
        }
    }

    float* out = (float*)d_out;

    init_kernel<<<157, 256>>>();
    main_kernel<<<1603, 256>>>(pred[0], pred[1], pred[2],
                               before[0], before[1], before[2],
                               lap[0], lap[1], lap[2],
                               gt_pts, gt_img, reconst);
    post_kernel<<<359, 256>>>(pred[0], pred[1], pred[2],
                              edges[0], edges[1], edges[2], gt_nrm);
    finalize_kernel<<<1, 32>>>(out);
}

// round 16
// speedup vs baseline: 1.9047x; 1.0547x over previous
#include <cuda_runtime.h>
#include <math.h>

#define NB 4
#define QN 10000

// Loss coefficients (compile-time): loss = sum over slots coef*partial_sum
#define C_PG0 (1.0f / (4.0f * 156.0f))
#define C_PG1 (1.0f / (4.0f * 618.0f))
#define C_PG2 (1.0f / (4.0f * 2466.0f))
#define C_GP  (0.55f / (4.0f * 10000.0f))
#define C_ED0 (0.1f / (4.0f * 462.0f))
#define C_ED1 (0.1f / (4.0f * 1848.0f))
#define C_ED2 (0.1f / (4.0f * 7392.0f))
#define C_NM0 (0.00016f / (4.0f * 462.0f))
#define C_NM1 (0.00016f / (4.0f * 1848.0f))
#define C_NM2 (0.00016f / (4.0f * 7392.0f))
#define C_LP0 (0.5f * 0.2f / (4.0f * 156.0f))
#define C_LP1 (0.5f * 1.0f / (4.0f * 618.0f))
#define C_LP2 (0.5f * 1.0f / (4.0f * 2466.0f))
#define C_MV0 0.0f
#define C_MV1 (0.1f * 1.0f / (4.0f * 618.0f))
#define C_MV2 (0.1f * 1.0f / (4.0f * 2466.0f))
#define C_BCE (-1.0f / (4.0f * 3.0f * 224.0f * 224.0f))

__device__ unsigned int       g_min32[9720];   // pg mins, n>0: lvl bases {0,468,2322}, idx (n-1)*P+p
__device__ unsigned long long g_min64[3240];   // pg batch-0: (key<<32)|gt_idx, lvl bases {0,156,774}
__device__ unsigned int       g_gp_min[40000]; // gp lvl2 mins: n*QN + q

__device__ __forceinline__ unsigned int fkey(float f) {
    unsigned int u = __float_as_uint(f);
    return (u & 0x80000000u) ? ~u : (u | 0x80000000u);
}
__device__ __forceinline__ float funkey(unsigned int k) {
    unsigned int u = (k & 0x80000000u) ? (k ^ 0x80000000u) : ~k;
    return __uint_as_float(u);
}
__device__ __forceinline__ float warpSum(float v) {
    #pragma unroll
    for (int o = 16; o > 0; o >>= 1) v += __shfl_down_sync(0xffffffffu, v, o);
    return v;
}

// ---- packed f32x2 FMA (FFMA2 — PTX only) ----------------------------------
union U64F2 { unsigned long long u; float2 f; };
__device__ __forceinline__ unsigned long long packf2(float x, float y) {
    U64F2 t; t.f.x = x; t.f.y = y; return t.u;
}
__device__ __forceinline__ float2 ffma2(unsigned long long a, unsigned long long b,
                                        unsigned long long c) {
    U64F2 d;
    asm("fma.rn.f32x2 %0, %1, %2, %3;" : "=l"(d.u) : "l"(a), "l"(b), "l"(c));
    return d.f;
}

// Packed tile loader: from 2 consecutive points (6 floats) build
// sA[t]=(x0,x1,y0,y1), sB[t]=(z0,z1,w0,w1), w = |pt|^2.
__device__ __forceinline__ void load_packed_tile(float4* sA, float4* sB,
                                                 const float* __restrict__ src,
                                                 int pairs, int tix) {
    for (int t = tix; t < pairs; t += 256) {
        const float2 v0 = *(const float2*)(src + 6 * t);       // x0 y0
        const float2 v1 = *(const float2*)(src + 6 * t + 2);   // z0 x1
        const float2 v2 = *(const float2*)(src + 6 * t + 4);   // y1 z1
        const float w0 = v0.x * v0.x + v0.y * v0.y + v1.x * v1.x;
        const float w1 = v1.y * v1.y + v2.x * v2.x + v2.y * v2.y;
        sA[t] = make_float4(v0.x, v1.y, v0.y, v2.x);
        sB[t] = make_float4(v1.x, v2.y, w0, w1);
    }
}

// Packed min scan tracking min of (|pt|^2 - 2*dot). 4 independent chains.
__device__ __forceinline__ float packed_min_scan(const float4* sA, const float4* sB,
                                                 int pairs,
                                                 unsigned long long mx2,
                                                 unsigned long long my2,
                                                 unsigned long long mz2) {
    float b0 = 3.4e38f, b1 = 3.4e38f, b2 = 3.4e38f, b3 = 3.4e38f;
    int t = 0;
    for (; t + 2 <= pairs; t += 2) {
        const float4 A0 = sA[t],     B0 = sB[t];
        const float4 A1 = sA[t + 1], B1 = sB[t + 1];
        float2 e0 = ffma2(mz2, packf2(B0.x, B0.y), packf2(B0.z, B0.w));
        float2 e1 = ffma2(mz2, packf2(B1.x, B1.y), packf2(B1.z, B1.w));
        e0 = ffma2(my2, packf2(A0.z, A0.w), packf2(e0.x, e0.y));
        e1 = ffma2(my2, packf2(A1.z, A1.w), packf2(e1.x, e1.y));
        e0 = ffma2(mx2, packf2(A0.x, A0.y), packf2(e0.x, e0.y));
        e1 = ffma2(mx2, packf2(A1.x, A1.y), packf2(e1.x, e1.y));
        b0 = fminf(b0, e0.x); b1 = fminf(b1, e0.y);
        b2 = fminf(b2, e1.x); b3 = fminf(b3, e1.y);
    }
    if (t < pairs) {
        const float4 A0 = sA[t], B0 = sB[t];
        float2 e0 = ffma2(mz2, packf2(B0.x, B0.y), packf2(B0.z, B0.w));
        e0 = ffma2(my2, packf2(A0.z, A0.w), packf2(e0.x, e0.y));
        e0 = ffma2(mx2, packf2(A0.x, A0.y), packf2(e0.x, e0.y));
        b0 = fminf(b0, e0.x); b1 = fminf(b1, e0.y);
    }
    return fminf(fminf(b0, b1), fminf(b2, b3));
}

// ---------------------------------------------------------------------------
__global__ void init_kernel(float* out) {
    const int i = blockIdx.x * blockDim.x + threadIdx.x;
    if (i == 0) out[0] = 0.0f;
    if (i < 9720) g_min32[i] = 0xFFFFFFFFu;
    if (i < 3240) g_min64[i] = 0xFFFFFFFFFFFFFFFFull;
    if (i < 40000) g_gp_min[i] = 0xFFFFFFFFu;
}

// ---------------------------------------------------------------------------
// Main kernel (256 threads). Block roles identical to the 78.3us config:
//   [0,560)     pg  (lvl0 [0,40), lvl1 [40,160), lvl2 [160,560)); 1000-pt GT chunks
//   [560,1360)  gp  (lvl0/1 full level one chunk direct weighted-sum; lvl2 3x822 scratch)
//   [1360,1411) lap+move  (single weighted atomic per warp)
//   [1411,1603) bce
// All direct sums go straight to out[0] pre-multiplied by their coefficient.
// ---------------------------------------------------------------------------
__global__ void __launch_bounds__(256) main_kernel(
    const float* __restrict__ p0, const float* __restrict__ p1, const float* __restrict__ p2,
    const float* __restrict__ be0, const float* __restrict__ be1, const float* __restrict__ be2,
    const int* __restrict__ l0, const int* __restrict__ l1, const int* __restrict__ l2i,
    const float* __restrict__ gt,
    const float* __restrict__ gt_img, const float* __restrict__ reconst,
    float* __restrict__ out) {
    __shared__ float4 s_buf[1000];
    float4* sA = s_buf;
    float4* sB = s_buf + 500;
    const int bid = blockIdx.x;
    const int tix = threadIdx.x;

    if (bid < 560) {
        // ----- pg: per pred point, min over a 1000-pt GT chunk (500 pairs) -----
        int r, P, lvl;
        const float* pred;
        if (bid < 40)       { lvl = 0; r = bid;       P = 156;  pred = p0; }
        else if (bid < 160) { lvl = 1; r = bid - 40;  P = 618;  pred = p1; }
        else                { lvl = 2; r = bid - 160; P = 2466; pred = p2; }
        const int gc = r % 10;
        const int n  = (r / 10) % NB;
        const int pc = r / 40;
        const int p  = pc * 256 + tix;
        const int base32[3] = {0, 468, 2322};
        const int base64[3] = {0, 156, 774};

        const float* g = gt + ((size_t)n * QN + gc * 1000) * 3;
        load_packed_tile(sA, sB, g, 500, tix);
        __syncthreads();
        if (p >= P) return;

        const float* pp = pred + ((size_t)n * P + p) * 3;
        const float px = pp[0], py = pp[1], pz = pp[2];
        const float x2 = px * px + py * py + pz * pz;
        const float mx = -2.f * px, my = -2.f * py, mz = -2.f * pz;

        if (n == 0) {
            // argmin path: scalar on the packed tile (2 pts per entry, 2 chains)
            float b0 = 3.4e38f, b1 = 3.4e38f;
            int i0 = 0, i1 = 1;
            for (int t = 0; t < 500; t++) {
                const float4 A = sA[t], B = sB[t];
                const float d0 = fmaf(mx, A.x, fmaf(my, A.z, fmaf(mz, B.x, B.z)));
                const float d1 = fmaf(mx, A.y, fmaf(my, A.w, fmaf(mz, B.y, B.w)));
                if (d0 < b0) { b0 = d0; i0 = 2 * t; }
                if (d1 < b1) { b1 = d1; i1 = 2 * t + 1; }
            }
            float best; int bi;
            if (b0 < b1 || (b0 == b1 && i0 < i1)) { best = b0; bi = i0; }
            else                                   { best = b1; bi = i1; }
            const unsigned int key = fkey(x2 + best);
            atomicMin(&g_min64[base64[lvl] + p],
                      ((unsigned long long)key << 32) | (unsigned int)(gc * 1000 + bi));
        } else {
            const unsigned long long mx2 = packf2(mx, mx);
            const unsigned long long my2 = packf2(my, my);
            const unsigned long long mz2 = packf2(mz, mz);
            const float best = x2 + packed_min_scan(sA, sB, 500, mx2, my2, mz2);
            atomicMin(&g_min32[base32[lvl] + (n - 1) * P + p], fkey(best));
        }
    } else if (bid < 1360) {
        // ----- gp: per GT point, min over pred chunk (packed FFMA2) -----
        const int r = bid - 560;
        int lvl, rr;
        if (r < 160)      { lvl = 0; rr = r; }
        else if (r < 320) { lvl = 1; rr = r - 160; }
        else              { lvl = 2; rr = r - 320; }
        int P; const float* pred;
        if (lvl == 0)      { P = 156;  pred = p0; }
        else if (lvl == 1) { P = 618;  pred = p1; }
        else               { P = 2466; pred = p2; }
        const int qc = rr % 40;
        const int t2 = rr / 40;
        const int n  = t2 % NB;
        const int pc = t2 / NB;              // 0 for lvl0/1; 0..2 for lvl2
        const int start = pc * 822;
        const int cnt = (lvl == 2) ? 822 : P;   // 822/156/618 — all even
        const int pairs = cnt / 2;

        const float* pr = pred + ((size_t)n * P + start) * 3;
        load_packed_tile(sA, sB, pr, pairs, tix);
        __syncthreads();

        const int q = qc * 256 + tix;
        const bool valid = (q < QN);
        float best = 0.f;
        if (valid) {
            const float* gq = gt + ((size_t)n * QN + q) * 3;
            const float qx = gq[0], qy = gq[1], qz = gq[2];
            const float q2 = qx * qx + qy * qy + qz * qz;
            const unsigned long long mx2 = packf2(-2.f * qx, -2.f * qx);
            const unsigned long long my2 = packf2(-2.f * qy, -2.f * qy);
            const unsigned long long mz2 = packf2(-2.f * qz, -2.f * qz);
            best = q2 + packed_min_scan(sA, sB, pairs, mx2, my2, mz2);
        }
        if (lvl < 2) {
            const float s = warpSum(valid ? best : 0.f);
            if ((tix & 31) == 0) atomicAdd(out, C_GP * s);
        } else {
            if (valid) atomicMin(&g_gp_min[n * QN + q], fkey(best));
        }
    } else if (bid < 1411) {
        // ----- laplace + move -----
        int i = (bid - 1360) * 256 + tix;
        float sl = 0.f, sm = 0.f;
        int lvl = -1;
        if (i < 12960) {
            int P; const float* pred; const float* bef; const int* lap;
            if (i < 624)       { lvl = 0; P = 156;  pred = p0; bef = be0; lap = l0; }
            else if (i < 3096) { lvl = 1; P = 618;  pred = p1; bef = be1; lap = l1; i -= 624; }
            else               { lvl = 2; P = 2466; pred = p2; bef = be2; lap = l2i; i -= 3096; }
            const int p = i % P;
            const int n = i / P;
            const int* lr = lap + (size_t)p * 10;
            const float invc = 1.f / (float)lr[9];
            const float* B  = bef  + (size_t)n * P * 3;
            const float* Pr = pred + (size_t)n * P * 3;
            float sbx = 0.f, sby = 0.f, sbz = 0.f;
            float spx = 0.f, spy = 0.f, spz = 0.f;
            #pragma unroll
            for (int j = 0; j < 8; j++) {
                const int k = lr[j];
                sbx += B[k * 3 + 0];  sby += B[k * 3 + 1];  sbz += B[k * 3 + 2];
                spx += Pr[k * 3 + 0]; spy += Pr[k * 3 + 1]; spz += Pr[k * 3 + 2];
            }
            const float bx = B[p * 3 + 0],  by = B[p * 3 + 1],  bz = B[p * 3 + 2];
            const float px = Pr[p * 3 + 0], py = Pr[p * 3 + 1], pz = Pr[p * 3 + 2];
            const float mvx = bx - px, mvy = by - py, mvz = bz - pz;
            const float dx = mvx - (sbx - spx) * invc;
            const float dy = mvy - (sby - spy) * invc;
            const float dz = mvz - (sbz - spz) * invc;
            sl = dx * dx + dy * dy + dz * dz;
            sm = mvx * mvx + mvy * mvy + mvz * mvz;
        }
        const float clap[3] = {C_LP0, C_LP1, C_LP2};
        const float cmov[3] = {C_MV0, C_MV1, C_MV2};
        const float w = (lvl >= 0) ? (clap[lvl] * sl + cmov[lvl] * sm) : 0.f;
        const float s = warpSum(w);
        if ((tix & 31) == 0) atomicAdd(out, s);
    } else {
        // ----- bce (grid-stride over images) -----
        const int N = NB * 3 * 224 * 224;
        const int stride = 192 * 256;
        float s = 0.f;
        for (int k = (bid - 1411) * 256 + tix; k < N; k += stride) {
            const float g = gt_img[k];
            const float rv = reconst[k];
            s += g * __logf(rv) + (1.f - g) * __logf(1.f - rv);
        }
        s = warpSum(s);
        if ((tix & 31) == 0) atomicAdd(out, C_BCE * s);
    }
}

// ---------------------------------------------------------------------------
// Post kernel: [0,207) scratch reduce (52960 entries), [207,359) edge+normal.
// All sums weighted and added directly to out[0]. No finalize kernel.
// ---------------------------------------------------------------------------
__global__ void __launch_bounds__(256) post_kernel(
    const float* __restrict__ p0, const float* __restrict__ p1, const float* __restrict__ p2,
    const int* __restrict__ e0, const int* __restrict__ e1, const int* __restrict__ e2,
    const float* __restrict__ gtn, float* __restrict__ out) {
    const int bid = blockIdx.x;
    const int tix = threadIdx.x;
    if (bid < 207) {
        const int j = bid * 256 + tix;
        float w = 0.f;
        if (j < 3240) {
            const float c = (j < 156) ? C_PG0 : (j < 774) ? C_PG1 : C_PG2;
            w = c * funkey((unsigned int)(g_min64[j] >> 32));
        } else if (j < 12960) {
            const int jj = j - 3240;
            const float c = (jj < 468) ? C_PG0 : (jj < 2322) ? C_PG1 : C_PG2;
            w = c * funkey(g_min32[jj]);
        } else if (j < 52960) {
            w = C_GP * funkey(g_gp_min[j - 12960]);
        }
        const float s = warpSum(w);
        if ((tix & 31) == 0) atomicAdd(out, s);
    } else {
        int i = (bid - 207) * 256 + tix;
        float w = 0.f;
        if (i < 38808) {
            int E, P, off;
            float ce, cn;
            const float* pred; const int* edges;
            if (i < 1848)      { E = 462;  P = 156;  off = 0;   pred = p0; edges = e0; ce = C_ED0; cn = C_NM0; }
            else if (i < 9240) { E = 1848; P = 618;  off = 156; pred = p1; edges = e1; ce = C_ED1; cn = C_NM1; i -= 1848; }
            else               { E = 7392; P = 2466; off = 774; pred = p2; edges = e2; ce = C_ED2; cn = C_NM2; i -= 9240; }
            const int e = i % E;
            const int n = i / E;
            const int a = edges[e * 2 + 0];
            const int b = edges[e * 2 + 1];
            const float* pa = pred + ((size_t)n * P + a) * 3;
            const float* pb = pred + ((size_t)n * P + b) * 3;
            const float dx = pa[0] - pb[0];
            const float dy = pa[1] - pb[1];
            const float dz = pa[2] - pb[2];
            const float l2 = dx * dx + dy * dy + dz * dz;
            const float inv_e = 1.f / fmaxf(sqrtf(l2), 1e-12f);
            const int gi = (int)(g_min64[off + a] & 0xFFFFFFFFull);
            const float* nr = gtn + ((size_t)n * QN + gi) * 3;
            const float nx = nr[0], ny = nr[1], nz = nr[2];
            const float inv_n = 1.f / fmaxf(sqrtf(nx * nx + ny * ny + nz * nz), 1e-12f);
            const float sn = fabsf((dx * nx + dy * ny + dz * nz) * inv_e * inv_n);
            w = ce * l2 + cn * sn;
        }
        const float s = warpSum(w);
        if ((tix & 31) == 0) atomicAdd(out, s);
    }
}

// ---------------------------------------------------------------------------
// Inputs classified BY ELEMENT COUNT (robust to metadata ordering).
// ---------------------------------------------------------------------------
extern "C" void kernel_launch(void* const* d_in, const int* in_sizes, int n_in,
                              void* d_out, int out_size) {
    const int szCoord[3] = {NB * 156 * 3, NB * 618 * 3, NB * 2466 * 3};
    const int szEdge[3]  = {462 * 2, 1848 * 2, 7392 * 2};
    const int szLap[3]   = {156 * 10, 618 * 10, 2466 * 10};
    const int szGt  = NB * QN * 3;
    const int szImg = NB * 3 * 224 * 224;

    const float* pred[3]   = {0, 0, 0};
    const float* before[3] = {0, 0, 0};
    const int*   edges[3]  = {0, 0, 0};
    const int*   lap[3]    = {0, 0, 0};
    const float* gt_pts = 0; const float* gt_nrm = 0;
    const float* gt_img = 0; const float* reconst = 0;

    for (int i = 0; i < n_in; i++) {
        const int s = in_sizes[i];
        bool done = false;
        for (int l = 0; l < 3 && !done; l++) {
            if (s == szCoord[l]) {
                if (!pred[l]) pred[l] = (const float*)d_in[i];
                else          before[l] = (const float*)d_in[i];
                done = true;
            } else if (s == szEdge[l]) {
                edges[l] = (const int*)d_in[i]; done = true;
            } else if (s == szLap[l]) {
                lap[l] = (const int*)d_in[i]; done = true;
            }
        }
        if (done) continue;
        if (s == szGt) {
            if (!gt_pts) gt_pts = (const float*)d_in[i];
            else         gt_nrm = (const float*)d_in[i];
        } else if (s == szImg) {
            if (!gt_img) gt_img = (const float*)d_in[i];
            else         reconst = (const float*)d_in[i];
        }
    }

    float* out = (float*)d_out;

    init_kernel<<<157, 256>>>(out);
    main_kernel<<<1603, 256>>>(pred[0], pred[1], pred[2],
                               before[0], before[1], before[2],
                               lap[0], lap[1], lap[2],
                               gt_pts, gt_img, reconst, out);
    post_kernel<<<359, 256>>>(pred[0], pred[1], pred[2],
                              edges[0], edges[1], edges[2], gt_nrm, out);
}